// round 3
// baseline (speedup 1.0000x reference)
#include <cuda_runtime.h>
#include <math.h>

// Problem constants
#define BATCH 512
#define HID   512
#define WDIM  1024
#define VOCAB 4004
#define TSTEPS 27
#define SLEN  80
#define NGATE 2048          // 4*HID
#define LSTM_IN 1536        // WDIM + HID

#define NB    888           // persistent grid (148 SMs x 6 blocks)

typedef unsigned long long ull;

// ---------------- scratch (device globals; allocation-free) ----------------
__device__ float g_a2[HID];
__device__ float g_a1[HID];
__device__ float g_a0e[HID];
__device__ float g_ctx[BATCH * HID];
__device__ float g_hbuf[2][BATCH * HID];
__device__ float g_c[BATCH * HID];
__device__ float g_Gbase[BATCH * NGATE];      // permuted cols: ctx @ W_ih_ctx^T + b_ih + b_hh
__device__ float g_Eproj[VOCAB * NGATE];      // permuted cols: embedding @ W_ih_word^T
__device__ ull   g_tokpack[2][BATCH];
__device__ unsigned g_bar_count;
__device__ unsigned g_bar_gen;

// ---------------- small helpers ----------------
__device__ __forceinline__ ull ffma2(ull a, ull b, ull c) {
    ull d;
    asm("fma.rn.f32x2 %0, %1, %2, %3;" : "=l"(d) : "l"(a), "l"(b), "l"(c));
    return d;
}
__device__ __forceinline__ ull bcast2(float x) {
    ull r;
    asm("mov.b64 %0, {%1, %2};" : "=l"(r) : "f"(x), "f"(x));
    return r;
}
__device__ __forceinline__ float2 unpack2(ull v) {
    float2 r;
    asm("mov.b64 {%0, %1}, %2;" : "=f"(r.x), "=f"(r.y) : "l"(v));
    return r;
}
__device__ __forceinline__ unsigned f2ord(float x) {
    unsigned u = __float_as_uint(x);
    return (u & 0x80000000u) ? ~u : (u | 0x80000000u);
}
__device__ __forceinline__ int decode_tok(ull p) {
    return (int)(0xFFFFFFFFu - (unsigned)(p & 0xFFFFFFFFull));
}
__device__ __forceinline__ float sigmoidf_(float x) {
    return 1.0f / (1.0f + expf(-x));
}
// gate-interleaved permutation: col n = unit*4+gate  ->  original row gate*512+unit
__device__ __forceinline__ int permrow(int n) {
    return ((n & 3) << 9) | (n >> 2);
}

// ---------------- grid-wide barrier (all NB blocks co-resident) -------------
__device__ __forceinline__ void grid_barrier() {
    __syncthreads();
    if (threadIdx.x == 0) {
        __threadfence();
        unsigned gen = *(volatile unsigned*)&g_bar_gen;
        if (atomicAdd(&g_bar_count, 1u) == (unsigned)(gridDim.x - 1)) {
            g_bar_count = 0;
            __threadfence();
            *(volatile unsigned*)&g_bar_gen = gen + 1;
        } else {
            while (*(volatile unsigned*)&g_bar_gen == gen) __nanosleep(20);
        }
        __threadfence();
    }
    __syncthreads();
}

// ---------------- init h, c, tokpack ----------------
__global__ void init_hc_kernel(const float* __restrict__ h0) {
    int b = blockIdx.x, u = threadIdx.x;
    g_hbuf[0][b * HID + u] = h0[b * HID + u];
    g_c[b * HID + u] = 0.0f;
    if (u == 0) { g_tokpack[0][b] = 0ull; g_tokpack[1][b] = 0ull; }
}

// ---------------- a-chain mat-vecs: out[j] = sum_h M[h,j] * vin[h] ----------
__global__ void matvecT_kernel(const float* __restrict__ Mt, int ld,
                               const float* __restrict__ vin_ext, int stage) {
    __shared__ float red[256];
    int j = blockIdx.x;
    const float* vin = (stage == 0) ? vin_ext : (stage == 1 ? g_a2 : g_a1);
    float acc = 0.0f;
    for (int h = threadIdx.x; h < HID; h += 256)
        acc += Mt[(size_t)h * ld + j] * vin[h];
    red[threadIdx.x] = acc;
    __syncthreads();
    for (int s = 128; s > 0; s >>= 1) {
        if (threadIdx.x < s) red[threadIdx.x] += red[threadIdx.x + s];
        __syncthreads();
    }
    if (threadIdx.x == 0) {
        float r = red[0];
        if (stage == 0)      g_a2[j]  = r;
        else if (stage == 1) g_a1[j]  = r;
        else                 g_a0e[j] = r;
    }
}

// ---------------- attention softmax + context (step-invariant) --------------
__global__ void attn_ctx_kernel(const float* __restrict__ enc) {
    __shared__ float sa[HID];
    __shared__ float sE[SLEN];
    __shared__ float sW[SLEN];
    int b = blockIdx.x;
    int tid = threadIdx.x;

    sa[tid]       = g_a0e[tid];
    sa[tid + 256] = g_a0e[tid + 256];
    __syncthreads();

    int w = tid >> 5, lane = tid & 31;
    for (int s = w; s < SLEN; s += 8) {
        const float* row = enc + ((size_t)b * SLEN + s) * HID;
        float acc = 0.0f;
        for (int k = lane; k < HID; k += 32) acc += row[k] * sa[k];
        #pragma unroll
        for (int off = 16; off > 0; off >>= 1)
            acc += __shfl_xor_sync(0xffffffffu, acc, off);
        if (lane == 0) sE[s] = acc;
    }
    __syncthreads();

    if (tid < 32) {
        float v0 = (tid      < SLEN) ? sE[tid]      : -INFINITY;
        float v1 = (tid + 32 < SLEN) ? sE[tid + 32] : -INFINITY;
        float v2 = (tid + 64 < SLEN) ? sE[tid + 64] : -INFINITY;
        float m = fmaxf(v0, fmaxf(v1, v2));
        #pragma unroll
        for (int off = 16; off > 0; off >>= 1)
            m = fmaxf(m, __shfl_xor_sync(0xffffffffu, m, off));
        float e0 = (tid      < SLEN) ? expf(v0 - m) : 0.0f;
        float e1 = (tid + 32 < SLEN) ? expf(v1 - m) : 0.0f;
        float e2 = (tid + 64 < SLEN) ? expf(v2 - m) : 0.0f;
        float s = e0 + e1 + e2;
        #pragma unroll
        for (int off = 16; off > 0; off >>= 1)
            s += __shfl_xor_sync(0xffffffffu, s, off);
        if (tid      < SLEN) sW[tid]      = e0 / s;
        if (tid + 32 < SLEN) sW[tid + 32] = e1 / s;
        if (tid + 64 < SLEN) sW[tid + 64] = e2 / s;
    }
    __syncthreads();

    for (int h = tid; h < HID; h += 256) {
        float acc = 0.0f;
        for (int s = 0; s < SLEN; s++)
            acc += sW[s] * enc[((size_t)b * SLEN + s) * HID + h];
        g_ctx[b * HID + h] = acc;
    }
}

// ---------------- precompute GEMM (BM=64 BN=64 BK=32, 256 thr, 4x4) --------
// MODE 0: Gbase = ctx @ W_ih_ctx^T (B rows permuted; +b_ih+b_hh permuted)
// MODE 3: Eproj = emb @ W_ih_word^T (B rows permuted)
template <int MODE>
__global__ __launch_bounds__(256, 3)
void pre_gemm_kernel(const float* __restrict__ Ap,
                     const float* __restrict__ Bp, int ldb,
                     int M, int N, int K,
                     const float* __restrict__ bias1,
                     const float* __restrict__ bias2) {
    __shared__ __align__(16) float As[32][68];
    __shared__ __align__(16) float Bs[32][68];

    const int tid = threadIdx.x;
    const int bm = blockIdx.y * 64;
    const int bn = blockIdx.x * 64;
    const int tm = tid >> 4;
    const int tn = tid & 15;

    const float* A = (MODE == 3) ? Ap : g_ctx;
    const int lda = (MODE == 3) ? WDIM : HID;

    ull acc[4][2];
    #pragma unroll
    for (int i = 0; i < 4; i++) { acc[i][0] = 0ull; acc[i][1] = 0ull; }

    const int lr = tid >> 3;
    const int lq = tid & 7;

    for (int k0 = 0; k0 < K; k0 += 32) {
        #pragma unroll
        for (int p = 0; p < 2; p++) {
            int r = lr + p * 32;
            int row = bm + r;
            float4 v = make_float4(0.f, 0.f, 0.f, 0.f);
            if (MODE != 3 || row < M)
                v = *reinterpret_cast<const float4*>(A + (size_t)row * lda + k0 + lq * 4);
            As[lq * 4 + 0][r] = v.x;
            As[lq * 4 + 1][r] = v.y;
            As[lq * 4 + 2][r] = v.z;
            As[lq * 4 + 3][r] = v.w;
        }
        #pragma unroll
        for (int p = 0; p < 2; p++) {
            int r = lr + p * 32;
            int brow = permrow(bn + r);
            float4 v = *reinterpret_cast<const float4*>(Bp + (size_t)brow * ldb + k0 + lq * 4);
            Bs[lq * 4 + 0][r] = v.x;
            Bs[lq * 4 + 1][r] = v.y;
            Bs[lq * 4 + 2][r] = v.z;
            Bs[lq * 4 + 3][r] = v.w;
        }
        __syncthreads();

        #pragma unroll
        for (int kk = 0; kk < 32; kk++) {
            float4 av = *reinterpret_cast<const float4*>(&As[kk][tm * 4]);
            ulonglong2 bv = *reinterpret_cast<const ulonglong2*>(&Bs[kk][tn * 4]);
            ull aa;
            aa = bcast2(av.x);
            acc[0][0] = ffma2(aa, bv.x, acc[0][0]);
            acc[0][1] = ffma2(aa, bv.y, acc[0][1]);
            aa = bcast2(av.y);
            acc[1][0] = ffma2(aa, bv.x, acc[1][0]);
            acc[1][1] = ffma2(aa, bv.y, acc[1][1]);
            aa = bcast2(av.z);
            acc[2][0] = ffma2(aa, bv.x, acc[2][0]);
            acc[2][1] = ffma2(aa, bv.y, acc[2][1]);
            aa = bcast2(av.w);
            acc[3][0] = ffma2(aa, bv.x, acc[3][0]);
            acc[3][1] = ffma2(aa, bv.y, acc[3][1]);
        }
        __syncthreads();
    }

    const int ncol = bn + tn * 4;
    float badd[4] = {0.f, 0.f, 0.f, 0.f};
    if (MODE == 0) {
        #pragma unroll
        for (int j = 0; j < 4; j++) {
            int pr = permrow(ncol + j);
            badd[j] = bias1[pr] + bias2[pr];
        }
    }
    float* Cbase = (MODE == 0) ? g_Gbase : g_Eproj;
    #pragma unroll
    for (int i = 0; i < 4; i++) {
        int m = bm + tm * 4 + i;
        if (MODE == 3 && m >= M) continue;
        float2 p0 = unpack2(acc[i][0]);
        float2 p1 = unpack2(acc[i][1]);
        float4 v = make_float4(p0.x + badd[0], p0.y + badd[1],
                               p1.x + badd[2], p1.y + badd[3]);
        *reinterpret_cast<float4*>(Cbase + (size_t)m * NGATE + ncol) = v;
    }
}

// ---------------- persistent decode kernel ----------------------------------
// 27 steps, each: Phase A (gates 64x32 tiles + fused LSTM) | barrier |
//                 Phase B (logits 64x32 tiles + store + argmax) | barrier
#define NT_A 512                 // (2048/32) * (512/64)
#define NTN_B 126                // ceil(4004/32)
#define NT_B (NTN_B * 8)         // 1008

__global__ __launch_bounds__(128, 6)
void decode_persistent(const float* __restrict__ Whh,
                       const float* __restrict__ Wout,
                       const float* __restrict__ out_b,
                       float* __restrict__ seq,
                       float* __restrict__ pred) {
    __shared__ __align__(16) float As[32][68];
    __shared__ __align__(16) float Bs[32][36];
    __shared__ int s_tok[64];

    const int tid = threadIdx.x;
    const int bid = blockIdx.x;
    const int tm = tid >> 3;      // 0..15
    const int tn = tid & 7;       // 0..7
    const int lq = tid & 7;       // 0..7 (float4 col)
    const int lr = tid >> 3;      // 0..15 (row base)

    for (int t = 0; t < TSTEPS; t++) {
        // ================= Phase A: gates + fused LSTM =================
        const float* hA = g_hbuf[t & 1];
        float* hW = g_hbuf[(t + 1) & 1];

        if (bid < NT_A) {
            const int tile = bid;
            const int bm = (tile & 7) * 64;
            const int bn = (tile >> 3) * 32;

            if (tid < 64)
                s_tok[tid] = (t == 0) ? 1 : decode_tok(g_tokpack[(t - 1) & 1][bm + tid]);

            ull acc[4][2];
            #pragma unroll
            for (int i = 0; i < 4; i++) { acc[i][0] = 0ull; acc[i][1] = 0ull; }

            for (int k0 = 0; k0 < HID; k0 += 32) {
                #pragma unroll
                for (int p = 0; p < 4; p++) {
                    int r = lr + p * 16;
                    float4 v = *reinterpret_cast<const float4*>(
                        hA + (size_t)(bm + r) * HID + k0 + lq * 4);
                    As[lq * 4 + 0][r] = v.x;
                    As[lq * 4 + 1][r] = v.y;
                    As[lq * 4 + 2][r] = v.z;
                    As[lq * 4 + 3][r] = v.w;
                }
                #pragma unroll
                for (int p = 0; p < 2; p++) {
                    int r = lr + p * 16;
                    int brow = permrow(bn + r);
                    float4 v = *reinterpret_cast<const float4*>(
                        Whh + (size_t)brow * HID + k0 + lq * 4);
                    Bs[lq * 4 + 0][r] = v.x;
                    Bs[lq * 4 + 1][r] = v.y;
                    Bs[lq * 4 + 2][r] = v.z;
                    Bs[lq * 4 + 3][r] = v.w;
                }
                __syncthreads();

                #pragma unroll
                for (int kk = 0; kk < 32; kk++) {
                    float4 av = *reinterpret_cast<const float4*>(&As[kk][tm * 4]);
                    ulonglong2 bv = *reinterpret_cast<const ulonglong2*>(&Bs[kk][tn * 4]);
                    ull aa;
                    aa = bcast2(av.x);
                    acc[0][0] = ffma2(aa, bv.x, acc[0][0]);
                    acc[0][1] = ffma2(aa, bv.y, acc[0][1]);
                    aa = bcast2(av.y);
                    acc[1][0] = ffma2(aa, bv.x, acc[1][0]);
                    acc[1][1] = ffma2(aa, bv.y, acc[1][1]);
                    aa = bcast2(av.z);
                    acc[2][0] = ffma2(aa, bv.x, acc[2][0]);
                    acc[2][1] = ffma2(aa, bv.y, acc[2][1]);
                    aa = bcast2(av.w);
                    acc[3][0] = ffma2(aa, bv.x, acc[3][0]);
                    acc[3][1] = ffma2(aa, bv.y, acc[3][1]);
                }
                __syncthreads();
            }

            // fused LSTM epilogue: 4 cols = (i,f,g,o) of unit u
            const int ncol = bn + tn * 4;
            const int u = ncol >> 2;
            #pragma unroll
            for (int i = 0; i < 4; i++) {
                int m = bm + tm * 4 + i;
                int tok = s_tok[tm * 4 + i];
                float2 p0 = unpack2(acc[i][0]);
                float2 p1 = unpack2(acc[i][1]);
                float4 gb = *reinterpret_cast<const float4*>(g_Gbase + (size_t)m * NGATE + ncol);
                float4 ep = *reinterpret_cast<const float4*>(g_Eproj + (size_t)tok * NGATE + ncol);
                float gi = p0.x + gb.x + ep.x;
                float gf = p0.y + gb.y + ep.y;
                float gg = p1.x + gb.z + ep.z;
                float go = p1.y + gb.w + ep.w;
                float c_old = g_c[m * HID + u];
                float cn = sigmoidf_(gf) * c_old + sigmoidf_(gi) * tanhf(gg);
                g_c[m * HID + u] = cn;
                hW[m * HID + u] = sigmoidf_(go) * tanhf(cn);
                if (bn == 0 && tn == 0 && t > 0 && pred)
                    pred[m * TSTEPS + (t - 1)] = (float)tok;
            }
        } else if (bid == NT_A) {
            // zero the tokpack buffer Phase B will atomicMax into
            for (int b = tid; b < BATCH; b += 128)
                g_tokpack[t & 1][b] = 0ull;
        }
        grid_barrier();

        // ================= Phase B: logits + argmax =================
        const float* hB = g_hbuf[(t + 1) & 1];
        for (int tile = bid; tile < NT_B; tile += NB) {
            const int bm = (tile & 7) * 64;
            const int bn = (tile >> 3) * 32;

            ull acc[4][2];
            #pragma unroll
            for (int i = 0; i < 4; i++) { acc[i][0] = 0ull; acc[i][1] = 0ull; }

            for (int k0 = 0; k0 < HID; k0 += 32) {
                #pragma unroll
                for (int p = 0; p < 4; p++) {
                    int r = lr + p * 16;
                    float4 v = *reinterpret_cast<const float4*>(
                        hB + (size_t)(bm + r) * HID + k0 + lq * 4);
                    As[lq * 4 + 0][r] = v.x;
                    As[lq * 4 + 1][r] = v.y;
                    As[lq * 4 + 2][r] = v.z;
                    As[lq * 4 + 3][r] = v.w;
                }
                #pragma unroll
                for (int p = 0; p < 2; p++) {
                    int r = lr + p * 16;
                    int row = bn + r;
                    float4 v = make_float4(0.f, 0.f, 0.f, 0.f);
                    if (row < VOCAB)
                        v = *reinterpret_cast<const float4*>(
                            Wout + (size_t)row * HID + k0 + lq * 4);
                    Bs[lq * 4 + 0][r] = v.x;
                    Bs[lq * 4 + 1][r] = v.y;
                    Bs[lq * 4 + 2][r] = v.z;
                    Bs[lq * 4 + 3][r] = v.w;
                }
                __syncthreads();

                #pragma unroll
                for (int kk = 0; kk < 32; kk++) {
                    float4 av = *reinterpret_cast<const float4*>(&As[kk][tm * 4]);
                    ulonglong2 bv = *reinterpret_cast<const ulonglong2*>(&Bs[kk][tn * 4]);
                    ull aa;
                    aa = bcast2(av.x);
                    acc[0][0] = ffma2(aa, bv.x, acc[0][0]);
                    acc[0][1] = ffma2(aa, bv.y, acc[0][1]);
                    aa = bcast2(av.y);
                    acc[1][0] = ffma2(aa, bv.x, acc[1][0]);
                    acc[1][1] = ffma2(aa, bv.y, acc[1][1]);
                    aa = bcast2(av.z);
                    acc[2][0] = ffma2(aa, bv.x, acc[2][0]);
                    acc[2][1] = ffma2(aa, bv.y, acc[2][1]);
                    aa = bcast2(av.w);
                    acc[3][0] = ffma2(aa, bv.x, acc[3][0]);
                    acc[3][1] = ffma2(aa, bv.y, acc[3][1]);
                }
                __syncthreads();
            }

            const int ncol = bn + tn * 4;
            #pragma unroll
            for (int i = 0; i < 4; i++) {
                int m = bm + tm * 4 + i;
                float cv[4];
                float2 p0 = unpack2(acc[i][0]);
                float2 p1 = unpack2(acc[i][1]);
                cv[0] = p0.x; cv[1] = p0.y; cv[2] = p1.x; cv[3] = p1.y;
                ull best = 0ull;
                #pragma unroll
                for (int j = 0; j < 4; j++) {
                    int n = ncol + j;
                    if (n < VOCAB) {
                        float v = cv[j] + out_b[n];
                        if (seq)
                            seq[(size_t)m * (TSTEPS * VOCAB) + (size_t)t * VOCAB + n] = v;
                        ull cand = ((ull)f2ord(v) << 32) | (ull)(0xFFFFFFFFu - (unsigned)n);
                        if (cand > best) best = cand;
                    }
                }
                #pragma unroll
                for (int off = 4; off > 0; off >>= 1) {
                    ull o = __shfl_xor_sync(0xffffffffu, best, off, 8);
                    if (o > best) best = o;
                }
                if (tn == 0) atomicMax(&g_tokpack[t & 1][m], best);
            }
        }
        grid_barrier();
    }

    // final pred for step TSTEPS-1 (tokpack[(TSTEPS-1)&1] == tokpack[0])
    if (bid == 0 && pred) {
        for (int b = tid; b < BATCH; b += 128)
            pred[b * TSTEPS + (TSTEPS - 1)] =
                (float)decode_tok(g_tokpack[(TSTEPS - 1) & 1][b]);
    }
}

// ---------------- launch ----------------
extern "C" void kernel_launch(void* const* d_in, const int* in_sizes, int n_in,
                              void* d_out, int out_size) {
    const float* enc_last = (const float*)d_in[0];   // [1,512,512]
    const float* enc_out  = (const float*)d_in[1];   // [512,80,512]
    const float* emb      = (const float*)d_in[2];   // [4004,1024]
    const float* w1       = (const float*)d_in[3];   // [512,1024]
    const float* w2       = (const float*)d_in[5];   // [512,512]
    const float* w3       = (const float*)d_in[7];   // [512,512]
    const float* wv       = (const float*)d_in[9];   // [1,512]
    const float* w_ih     = (const float*)d_in[10];  // [2048,1536]
    const float* w_hh     = (const float*)d_in[11];  // [2048,512]
    const float* b_ih     = (const float*)d_in[12];  // [2048]
    const float* b_hh     = (const float*)d_in[13];  // [2048]
    const float* out_w    = (const float*)d_in[14];  // [4004,512]
    const float* out_b    = (const float*)d_in[15];  // [4004]

    float* out = (float*)d_out;
    const long long SEQ  = (long long)BATCH * TSTEPS * VOCAB;
    const long long PRED = (long long)BATCH * TSTEPS;
    float* seq_ptr  = ((long long)out_size >= SEQ) ? out : nullptr;
    float* pred_ptr = ((long long)out_size >= SEQ + PRED) ? (out + SEQ) : nullptr;

    // --- precompute
    init_hc_kernel<<<BATCH, HID>>>(enc_last);
    matvecT_kernel<<<HID, 256>>>(w3, HID, wv, 0);       // a2 = W3^T wv
    matvecT_kernel<<<HID, 256>>>(w2, HID, nullptr, 1);  // a1 = W2^T a2
    matvecT_kernel<<<HID, 256>>>(w1, WDIM, nullptr, 2); // a0e = (W1^T a1)[:512]
    attn_ctx_kernel<<<BATCH, 256>>>(enc_out);

    // G_base (permuted cols) = ctx @ W_ih_ctx^T + b_ih + b_hh
    pre_gemm_kernel<0><<<dim3(NGATE / 64, BATCH / 64), 256>>>(
        nullptr, w_ih + WDIM, LSTM_IN, BATCH, NGATE, HID, b_ih, b_hh);

    // E_proj (permuted cols) = embedding @ W_ih_word^T
    pre_gemm_kernel<3><<<dim3(NGATE / 64, (VOCAB + 63) / 64), 256>>>(
        emb, w_ih, LSTM_IN, VOCAB, NGATE, WDIM, nullptr, nullptr);

    // --- all 27 decode steps in ONE persistent kernel
    decode_persistent<<<NB, 128>>>(w_hh, out_w, out_b, seq_ptr, pred_ptr);
}

// round 4
// speedup vs baseline: 1.3137x; 1.3137x over previous
#include <cuda_runtime.h>
#include <math.h>
#include <stdint.h>

// Problem constants
#define BATCH 512
#define HID   512
#define WDIM  1024
#define VOCAB 4004
#define TSTEPS 27
#define SLEN  80
#define NGATE 2048          // 4*HID
#define LSTM_IN 1536        // WDIM + HID

typedef unsigned long long ull;

// ---------------- scratch (device globals; allocation-free) ----------------
__device__ float g_a2[HID];
__device__ float g_a1[HID];
__device__ float g_a0e[HID];
__device__ float g_ctx[BATCH * HID];
__device__ float g_hbuf[2][BATCH * HID];
__device__ float g_c[BATCH * HID];
__device__ float g_Gbase[BATCH * NGATE];      // permuted cols: ctx @ W_ih_ctx^T + b_ih + b_hh
__device__ float g_Eproj[VOCAB * NGATE];      // permuted cols: embedding @ W_ih_word^T
__device__ ull   g_tokpack[2][BATCH];

// ---------------- small helpers ----------------
__device__ __forceinline__ ull ffma2(ull a, ull b, ull c) {
    ull d;
    asm("fma.rn.f32x2 %0, %1, %2, %3;" : "=l"(d) : "l"(a), "l"(b), "l"(c));
    return d;
}
__device__ __forceinline__ float2 unpack2(ull v) {
    float2 r;
    asm("mov.b64 {%0, %1}, %2;" : "=f"(r.x), "=f"(r.y) : "l"(v));
    return r;
}
__device__ __forceinline__ unsigned f2ord(float x) {
    unsigned u = __float_as_uint(x);
    return (u & 0x80000000u) ? ~u : (u | 0x80000000u);
}
__device__ __forceinline__ int decode_tok(ull p) {
    return (int)(0xFFFFFFFFu - (unsigned)(p & 0xFFFFFFFFull));
}
__device__ __forceinline__ float sigmoidf_(float x) {
    return 1.0f / (1.0f + expf(-x));
}
// gate-interleaved permutation: col n = unit*4+gate  ->  original row gate*512+unit
__device__ __forceinline__ int permrow(int n) {
    return ((n & 3) << 9) | (n >> 2);
}

#define CP_ASYNC16(dst, src, sz) \
    asm volatile("cp.async.cg.shared.global [%0], [%1], 16, %2;\n" \
                 :: "r"(dst), "l"(src), "r"(sz))
#define CP_COMMIT() asm volatile("cp.async.commit_group;\n")
#define CP_WAIT1()  asm volatile("cp.async.wait_group 1;\n")
#define CP_WAIT0()  asm volatile("cp.async.wait_group 0;\n")

// ---------------- init h, c, tokpack ----------------
__global__ void init_hc_kernel(const float* __restrict__ h0) {
    int b = blockIdx.x, u = threadIdx.x;
    g_hbuf[0][b * HID + u] = h0[b * HID + u];
    g_c[b * HID + u] = 0.0f;
    if (u == 0) { g_tokpack[0][b] = 0ull; g_tokpack[1][b] = 0ull; }
}

// ---------------- a-chain mat-vecs: out[j] = sum_h M[h,j] * vin[h] ----------
__global__ void matvecT_kernel(const float* __restrict__ Mt, int ld,
                               const float* __restrict__ vin_ext, int stage) {
    __shared__ float red[256];
    int j = blockIdx.x;
    const float* vin = (stage == 0) ? vin_ext : (stage == 1 ? g_a2 : g_a1);
    float acc = 0.0f;
    for (int h = threadIdx.x; h < HID; h += 256)
        acc += Mt[(size_t)h * ld + j] * vin[h];
    red[threadIdx.x] = acc;
    __syncthreads();
    for (int s = 128; s > 0; s >>= 1) {
        if (threadIdx.x < s) red[threadIdx.x] += red[threadIdx.x + s];
        __syncthreads();
    }
    if (threadIdx.x == 0) {
        float r = red[0];
        if (stage == 0)      g_a2[j]  = r;
        else if (stage == 1) g_a1[j]  = r;
        else                 g_a0e[j] = r;
    }
}

// ---------------- attention softmax + context (step-invariant) --------------
__global__ void attn_ctx_kernel(const float* __restrict__ enc) {
    __shared__ float sa[HID];
    __shared__ float sE[SLEN];
    __shared__ float sW[SLEN];
    int b = blockIdx.x;
    int tid = threadIdx.x;

    sa[tid]       = g_a0e[tid];
    sa[tid + 256] = g_a0e[tid + 256];
    __syncthreads();

    int w = tid >> 5, lane = tid & 31;
    for (int s = w; s < SLEN; s += 8) {
        const float* row = enc + ((size_t)b * SLEN + s) * HID;
        float acc = 0.0f;
        for (int k = lane; k < HID; k += 32) acc += row[k] * sa[k];
        #pragma unroll
        for (int off = 16; off > 0; off >>= 1)
            acc += __shfl_xor_sync(0xffffffffu, acc, off);
        if (lane == 0) sE[s] = acc;
    }
    __syncthreads();

    if (tid < 32) {
        float v0 = (tid      < SLEN) ? sE[tid]      : -INFINITY;
        float v1 = (tid + 32 < SLEN) ? sE[tid + 32] : -INFINITY;
        float v2 = (tid + 64 < SLEN) ? sE[tid + 64] : -INFINITY;
        float m = fmaxf(v0, fmaxf(v1, v2));
        #pragma unroll
        for (int off = 16; off > 0; off >>= 1)
            m = fmaxf(m, __shfl_xor_sync(0xffffffffu, m, off));
        float e0 = (tid      < SLEN) ? expf(v0 - m) : 0.0f;
        float e1 = (tid + 32 < SLEN) ? expf(v1 - m) : 0.0f;
        float e2 = (tid + 64 < SLEN) ? expf(v2 - m) : 0.0f;
        float s = e0 + e1 + e2;
        #pragma unroll
        for (int off = 16; off > 0; off >>= 1)
            s += __shfl_xor_sync(0xffffffffu, s, off);
        if (tid      < SLEN) sW[tid]      = e0 / s;
        if (tid + 32 < SLEN) sW[tid + 32] = e1 / s;
        if (tid + 64 < SLEN) sW[tid + 64] = e2 / s;
    }
    __syncthreads();

    for (int h = tid; h < HID; h += 256) {
        float acc = 0.0f;
        for (int s = 0; s < SLEN; s++)
            acc += sW[s] * enc[((size_t)b * SLEN + s) * HID + h];
        g_ctx[b * HID + h] = acc;
    }
}

// ---------------- K-packed fp32x2 GEMM, BM=64 BN=64 BK=32, 128 thr, 4x8 ----
// C[m,n] = sum_k A[m,k]*B[n,k]; f32x2 lanes carry (even-k, odd-k) partials.
// cp.async 2-stage pipeline; XOR-swizzled K-contiguous smem tiles.
// MODE 0: Gbase  = ctx @ W_ih_ctx^T (B rows permuted; +b_ih+b_hh permuted)
// MODE 1: gates  = h @ W_hh^T (perm) + Gbase + Eproj[tok]; fused LSTM -> h,c
// MODE 2: logits = h @ out_w^T + out_b; store seq + fused argmax
// MODE 3: Eproj  = emb @ W_ih_word^T (B rows permuted)
template <int MODE>
__global__ __launch_bounds__(128, 4)
void gemm_kernel(const float* __restrict__ Ap,
                 const float* __restrict__ Bp, int ldb,
                 float* __restrict__ Cp,
                 int M, int N, int K,
                 const float* __restrict__ bias1,
                 const float* __restrict__ bias2,
                 int t, float* __restrict__ pred) {
    __shared__ __align__(16) float As[2][64 * 32];
    __shared__ __align__(16) float Bs[2][64 * 32];
    __shared__ int s_tok[64];

    const int tid = threadIdx.x;
    const int bm = blockIdx.y * 64;
    const int bn = blockIdx.x * 64;
    const int tm = tid >> 3;   // 0..15 -> rows tm*4..tm*4+3
    const int tn = tid & 7;    // 0..7  -> cols tn*8..tn*8+7

    const float* A;
    int lda;
    if (MODE == 3)      { A = Ap;    lda = WDIM; }
    else if (MODE == 0) { A = g_ctx; lda = HID; }
    else                { A = g_hbuf[(MODE == 1) ? (t & 1) : ((t + 1) & 1)]; lda = HID; }

    if (MODE == 1 && tid < 64)
        s_tok[tid] = (t == 0) ? 1 : decode_tok(g_tokpack[(t - 1) & 1][bm + tid]);
    if (MODE == 2 && blockIdx.x == 0 && tid < 64)
        g_tokpack[(t + 1) & 1][bm + tid] = 0ull;   // prep buffer for next step

    const uint32_t sA = (uint32_t)__cvta_generic_to_shared(&As[0][0]);
    const uint32_t sB = (uint32_t)__cvta_generic_to_shared(&Bs[0][0]);

    // per-thread loader geometry: row = tid>>1 (0..63), chunk base = (tid&1)*4
    const int ldrow = tid >> 1;
    const int ldcb  = (tid & 1) * 4;
    const int aswz  = (ldrow >> 2) & 7;
    const int bswz  = (ldrow >> 3) & 7;

    // A source row (MODE 3 may be out of range)
    int agr = bm + ldrow;
    int a_sz = 16;
    if (MODE == 3 && agr >= M) { a_sz = 0; agr = 0; }
    const float* a_srcbase = A + (size_t)agr * lda + ldcb * 4;

    // B source row
    int bgr = bn + ldrow;
    int b_sz = 16;
    int brow;
    if (MODE == 2) {
        if (bgr >= N) { b_sz = 0; brow = 0; } else brow = bgr;
    } else {
        brow = permrow(bgr);
    }
    const float* b_srcbase = Bp + (size_t)brow * ldb + ldcb * 4;

    const uint32_t a_dst = sA + ldrow * 128;
    const uint32_t b_dst = sB + ldrow * 128;

    ull acc[4][8];
    #pragma unroll
    for (int i = 0; i < 4; i++)
        #pragma unroll
        for (int j = 0; j < 8; j++) acc[i][j] = 0ull;

    const int nch = K >> 5;

    // prologue: stage 0
    {
        #pragma unroll
        for (int jj = 0; jj < 4; jj++) {
            int c = ldcb + jj;
            CP_ASYNC16(a_dst + (((c ^ aswz)) << 4), a_srcbase + jj * 4, a_sz);
            CP_ASYNC16(b_dst + (((c ^ bswz)) << 4), b_srcbase + jj * 4, b_sz);
        }
        CP_COMMIT();
    }

    for (int ch = 0; ch < nch; ch++) {
        if (ch + 1 < nch) {
            int k0 = (ch + 1) << 5;
            uint32_t soff = ((ch + 1) & 1) ? 8192u : 0u;
            #pragma unroll
            for (int jj = 0; jj < 4; jj++) {
                int c = ldcb + jj;
                CP_ASYNC16(a_dst + soff + ((c ^ aswz) << 4), a_srcbase + k0 + jj * 4, a_sz);
                CP_ASYNC16(b_dst + soff + ((c ^ bswz) << 4), b_srcbase + k0 + jj * 4, b_sz);
            }
            CP_COMMIT();
            CP_WAIT1();
        } else {
            CP_WAIT0();
        }
        __syncthreads();

        const float* as = As[ch & 1];
        const float* bs = Bs[ch & 1];
        #pragma unroll
        for (int c = 0; c < 8; c++) {
            const int aoff = (c ^ (tm & 7)) << 2;
            const int boff = (c ^ tn) << 2;
            ulonglong2 av0 = *(const ulonglong2*)&as[(tm * 4 + 0) * 32 + aoff];
            ulonglong2 av1 = *(const ulonglong2*)&as[(tm * 4 + 1) * 32 + aoff];
            ulonglong2 av2 = *(const ulonglong2*)&as[(tm * 4 + 2) * 32 + aoff];
            ulonglong2 av3 = *(const ulonglong2*)&as[(tm * 4 + 3) * 32 + aoff];
            #pragma unroll
            for (int j = 0; j < 8; j++) {
                ulonglong2 bv = *(const ulonglong2*)&bs[(tn * 8 + j) * 32 + boff];
                acc[0][j] = ffma2(av0.x, bv.x, acc[0][j]);
                acc[0][j] = ffma2(av0.y, bv.y, acc[0][j]);
                acc[1][j] = ffma2(av1.x, bv.x, acc[1][j]);
                acc[1][j] = ffma2(av1.y, bv.y, acc[1][j]);
                acc[2][j] = ffma2(av2.x, bv.x, acc[2][j]);
                acc[2][j] = ffma2(av2.y, bv.y, acc[2][j]);
                acc[3][j] = ffma2(av3.x, bv.x, acc[3][j]);
                acc[3][j] = ffma2(av3.y, bv.y, acc[3][j]);
            }
        }
        __syncthreads();
    }

    // lane-sum: cv[i][j] = even-k partial + odd-k partial
    float cv[4][8];
    #pragma unroll
    for (int i = 0; i < 4; i++)
        #pragma unroll
        for (int j = 0; j < 8; j++) {
            float2 p = unpack2(acc[i][j]);
            cv[i][j] = p.x + p.y;
        }

    const int ncol = bn + tn * 8;

    if (MODE == 0 || MODE == 3) {
        float badd[8];
        #pragma unroll
        for (int j = 0; j < 8; j++) {
            if (MODE == 0) {
                int pr = permrow(ncol + j);
                badd[j] = bias1[pr] + bias2[pr];
            } else badd[j] = 0.0f;
        }
        float* Cb = (MODE == 0) ? g_Gbase : g_Eproj;
        #pragma unroll
        for (int i = 0; i < 4; i++) {
            int m = bm + tm * 4 + i;
            if (MODE == 3 && m >= M) continue;
            float4 v0 = make_float4(cv[i][0] + badd[0], cv[i][1] + badd[1],
                                    cv[i][2] + badd[2], cv[i][3] + badd[3]);
            float4 v1 = make_float4(cv[i][4] + badd[4], cv[i][5] + badd[5],
                                    cv[i][6] + badd[6], cv[i][7] + badd[7]);
            *reinterpret_cast<float4*>(Cb + (size_t)m * NGATE + ncol)     = v0;
            *reinterpret_cast<float4*>(Cb + (size_t)m * NGATE + ncol + 4) = v1;
        }
    } else if (MODE == 1) {
        // fused LSTM: cols = two (i,f,g,o) quadruples for units u0, u0+1
        const int u0 = ncol >> 2;
        float* hW = g_hbuf[(t + 1) & 1];
        #pragma unroll
        for (int i = 0; i < 4; i++) {
            int m = bm + tm * 4 + i;
            int tok = s_tok[tm * 4 + i];
            float4 gb0 = *reinterpret_cast<const float4*>(g_Gbase + (size_t)m * NGATE + ncol);
            float4 gb1 = *reinterpret_cast<const float4*>(g_Gbase + (size_t)m * NGATE + ncol + 4);
            float4 ep0 = *reinterpret_cast<const float4*>(g_Eproj + (size_t)tok * NGATE + ncol);
            float4 ep1 = *reinterpret_cast<const float4*>(g_Eproj + (size_t)tok * NGATE + ncol + 4);
            {
                float gi = cv[i][0] + gb0.x + ep0.x;
                float gf = cv[i][1] + gb0.y + ep0.y;
                float gg = cv[i][2] + gb0.z + ep0.z;
                float go = cv[i][3] + gb0.w + ep0.w;
                float c_old = g_c[m * HID + u0];
                float cn = sigmoidf_(gf) * c_old + sigmoidf_(gi) * tanhf(gg);
                g_c[m * HID + u0] = cn;
                hW[m * HID + u0] = sigmoidf_(go) * tanhf(cn);
            }
            {
                float gi = cv[i][4] + gb1.x + ep1.x;
                float gf = cv[i][5] + gb1.y + ep1.y;
                float gg = cv[i][6] + gb1.z + ep1.z;
                float go = cv[i][7] + gb1.w + ep1.w;
                float c_old = g_c[m * HID + u0 + 1];
                float cn = sigmoidf_(gf) * c_old + sigmoidf_(gi) * tanhf(gg);
                g_c[m * HID + u0 + 1] = cn;
                hW[m * HID + u0 + 1] = sigmoidf_(go) * tanhf(cn);
            }
            if (blockIdx.x == 0 && tn == 0 && t > 0 && pred)
                pred[m * TSTEPS + (t - 1)] = (float)tok;
        }
    } else {  // MODE 2: logits + argmax
        #pragma unroll
        for (int i = 0; i < 4; i++) {
            int m = bm + tm * 4 + i;
            float v[8];
            ull best = 0ull;
            #pragma unroll
            for (int j = 0; j < 8; j++) {
                int n = ncol + j;
                v[j] = cv[i][j] + ((n < N) ? bias1[n] : 0.0f);
                if (n < N) {
                    ull cand = ((ull)f2ord(v[j]) << 32) | (ull)(0xFFFFFFFFu - (unsigned)n);
                    if (cand > best) best = cand;
                }
            }
            if (Cp) {
                float* orow = Cp + (size_t)m * (TSTEPS * VOCAB) + (size_t)t * VOCAB;
                if (ncol + 7 < N) {
                    *reinterpret_cast<float4*>(orow + ncol)     = make_float4(v[0], v[1], v[2], v[3]);
                    *reinterpret_cast<float4*>(orow + ncol + 4) = make_float4(v[4], v[5], v[6], v[7]);
                } else {
                    #pragma unroll
                    for (int j = 0; j < 8; j++)
                        if (ncol + j < N) orow[ncol + j] = v[j];
                }
            }
            #pragma unroll
            for (int off = 4; off > 0; off >>= 1) {
                ull o = __shfl_xor_sync(0xffffffffu, best, off, 8);
                if (o > best) best = o;
            }
            if (tn == 0) atomicMax(&g_tokpack[t & 1][m], best);
        }
    }
}

// ---------------- final pred ----------------
__global__ void final_pred_kernel(float* __restrict__ pred) {
    int b = threadIdx.x;
    pred[b * TSTEPS + (TSTEPS - 1)] = (float)decode_tok(g_tokpack[(TSTEPS - 1) & 1][b]);
}

// ---------------- launch ----------------
extern "C" void kernel_launch(void* const* d_in, const int* in_sizes, int n_in,
                              void* d_out, int out_size) {
    const float* enc_last = (const float*)d_in[0];   // [1,512,512]
    const float* enc_out  = (const float*)d_in[1];   // [512,80,512]
    const float* emb      = (const float*)d_in[2];   // [4004,1024]
    const float* w1       = (const float*)d_in[3];   // [512,1024]
    const float* w2       = (const float*)d_in[5];   // [512,512]
    const float* w3       = (const float*)d_in[7];   // [512,512]
    const float* wv       = (const float*)d_in[9];   // [1,512]
    const float* w_ih     = (const float*)d_in[10];  // [2048,1536]
    const float* w_hh     = (const float*)d_in[11];  // [2048,512]
    const float* b_ih     = (const float*)d_in[12];  // [2048]
    const float* b_hh     = (const float*)d_in[13];  // [2048]
    const float* out_w    = (const float*)d_in[14];  // [4004,512]
    const float* out_b    = (const float*)d_in[15];  // [4004]

    float* out = (float*)d_out;
    const long long SEQ  = (long long)BATCH * TSTEPS * VOCAB;
    const long long PRED = (long long)BATCH * TSTEPS;
    float* seq_ptr  = ((long long)out_size >= SEQ) ? out : nullptr;
    float* pred_ptr = ((long long)out_size >= SEQ + PRED) ? (out + SEQ) : nullptr;

    // --- precompute
    init_hc_kernel<<<BATCH, HID>>>(enc_last);
    matvecT_kernel<<<HID, 256>>>(w3, HID, wv, 0);       // a2 = W3^T wv
    matvecT_kernel<<<HID, 256>>>(w2, HID, nullptr, 1);  // a1 = W2^T a2
    matvecT_kernel<<<HID, 256>>>(w1, WDIM, nullptr, 2); // a0e = (W1^T a1)[:512]
    attn_ctx_kernel<<<BATCH, 256>>>(enc_out);

    // G_base (permuted cols) = ctx @ W_ih_ctx^T + b_ih + b_hh
    gemm_kernel<0><<<dim3(NGATE / 64, BATCH / 64), 128>>>(
        nullptr, w_ih + WDIM, LSTM_IN, nullptr,
        BATCH, NGATE, HID, b_ih, b_hh, 0, nullptr);

    // E_proj (permuted cols) = embedding @ W_ih_word^T
    gemm_kernel<3><<<dim3(NGATE / 64, (VOCAB + 63) / 64), 128>>>(
        emb, w_ih, LSTM_IN, nullptr,
        VOCAB, NGATE, WDIM, nullptr, nullptr, 0, nullptr);

    // --- 27 sequential decode steps (2 launches each)
    for (int t = 0; t < TSTEPS; t++) {
        // gates + fused LSTM -> h_new, c ; also writes pred[t-1]
        gemm_kernel<1><<<dim3(NGATE / 64, BATCH / 64), 128>>>(
            nullptr, w_hh, HID, nullptr,
            BATCH, NGATE, HID, nullptr, nullptr, t, pred_ptr);
        // logits + bias + store + fused argmax
        gemm_kernel<2><<<dim3((VOCAB + 63) / 64, BATCH / 64), 128>>>(
            nullptr, out_w, HID, seq_ptr,
            BATCH, VOCAB, HID, out_b, nullptr, t, nullptr);
    }
    if (pred_ptr)
        final_pred_kernel<<<1, BATCH>>>(pred_ptr);
}